// round 16
// baseline (speedup 1.0000x reference)
#include <cuda_runtime.h>

#define VSZ 50257
#define Dk  50
#define TT  1024
#define BSZ 1024
#define BB  4
#define NT  352

// Precomputed emb @ kx1 + b1[0] table: [V, 96] fp32 (L2-resident, 19.3MB)
__device__ float g_proj1[VSZ * 96];

typedef unsigned long long u64;

__device__ __forceinline__ u64 pk2(float a, float b) {
    u64 r; asm("mov.b64 %0, {%1, %2};" : "=l"(r) : "f"(a), "f"(b)); return r;
}
__device__ __forceinline__ void upk2(u64 v, float& a, float& b) {
    asm("mov.b64 {%0, %1}, %2;" : "=f"(a), "=f"(b) : "l"(v));
}
__device__ __forceinline__ u64 ffma2(u64 a, u64 b, u64 c) {
    u64 d; asm("fma.rn.f32x2 %0, %1, %2, %3;" : "=l"(d) : "l"(a), "l"(b), "l"(c)); return d;
}
// exact (epilogue only)
__device__ __forceinline__ float sgm(float x) { return 1.0f / (1.0f + __expf(-x)); }
// HW tanh path (hot loop): 1 MUFU per evaluation
__device__ __forceinline__ float tanha(float x) {
    float y; asm("tanh.approx.f32 %0, %1;" : "=f"(y) : "f"(x)); return y;
}
__device__ __forceinline__ float sgm_fast(float x) {
    return fmaf(tanha(0.5f * x), 0.5f, 0.5f);
}

__device__ __forceinline__ float gru1s(float xz, float hz, float xr, float hr,
                                       float xh, float hh, float hold) {
    float z = sgm_fast(xz + hz);
    float r = sgm_fast(xr + hr);
    float c = tanha(xh + r * hh);
    return fmaf(z, hold - c, c);     // z*h + (1-z)*c
}

__device__ __forceinline__ void bar_sync_r(int id, int cnt) {
    asm volatile("bar.sync %0, %1;" :: "r"(id), "r"(cnt) : "memory");
}
__device__ __forceinline__ void bar_arrive_r(int id, int cnt) {
    asm volatile("bar.arrive %0, %1;" :: "r"(id), "r"(cnt) : "memory");
}
#define BAR_SYNC(id, cnt) asm volatile("bar.sync %0, %1;" :: "n"(id), "n"(cnt) : "memory")

// ---------------------------------------------------------------------------
__global__ void proj_kernel(const float* __restrict__ emb,
                            const float* __restrict__ kx1,
                            const float* __restrict__ b1) {
    __shared__ float kxs[Dk * 96];
    __shared__ float embs[16 * Dk];
    int tid = threadIdx.x;
    for (int i = tid; i < Dk * 96; i += 256) kxs[i] = kx1[i];
    int vbase = blockIdx.x * 16;
    for (int i = tid; i < 16 * Dk; i += 256) {
        int r = i / Dk, d = i - r * Dk;
        int v = vbase + r;
        embs[i] = (v < VSZ) ? emb[v * Dk + d] : 0.0f;
    }
    __syncthreads();
    for (int i = tid; i < 16 * 96; i += 256) {
        int r = i / 96, j = i - r * 96;
        int v = vbase + r;
        if (v >= VSZ) continue;
        float acc = b1[j];
        #pragma unroll
        for (int d = 0; d < Dk; d++)
            acc = fmaf(embs[r * Dk + d], kxs[d * 96 + j], acc);
        g_proj1[v * 96 + j] = acc;
    }
}

// ---------------------------------------------------------------------------
// Shared layout (bytes), BB=4 batches per CTA.
// States: [u][6] u64 rows (48B, 16B-aligned; dup pairs (h,h), slots 0-3 = b).
// P3: 4 u-half bufs x [4][192] f32 (group2 internal).
// P2: 4 parity x 2 u-half bufs x [4][192] f32 (cross, 4-deep pipeline).
// P1: 2 u-half bufs x [4][96] f32 (group1 internal).
// ---------------------------------------------------------------------------
#define OFF_H1S  0        // 1536
#define OFF_H2S  1536     // 3072
#define OFF_P3   4608     // 12288
#define OFF_P2   16896    // 24576 (parity*1536fl + uh*768fl)
#define OFF_P1   41472    // 3072
#define OFF_XG1  44544    // 3072
#define OFF_TOK  47616    // 512
#define SMEM_SZ  48128

__global__ void __launch_bounds__(NT, 2) rnn_kernel(
    const int*   __restrict__ tokens,
    const float* __restrict__ kh1,   // [32][96]
    const float* __restrict__ b1,    // [2][96]
    const float* __restrict__ kx2,   // [32][192]
    const float* __restrict__ kh2,   // [64][192]
    const float* __restrict__ b2,    // [2][192]
    const float* __restrict__ wg,    // [64][256]
    const float* __restrict__ bg,    // [256]
    const float* __restrict__ wd,    // [128]
    const float* __restrict__ bd,    // [1]
    float*       __restrict__ out)
{
    extern __shared__ char sbuf[];
    u64*   h1s = (u64*)(sbuf + OFF_H1S);   // [u][6]
    u64*   h2s = (u64*)(sbuf + OFF_H2S);   // [u][6]
    float* P3f = (float*)(sbuf + OFF_P3);
    float* P2f = (float*)(sbuf + OFF_P2);
    float* P1f = (float*)(sbuf + OFF_P1);
    float* xg1 = (float*)(sbuf + OFF_XG1); // 2 bufs x 384 floats
    int*   tok = (int*)(sbuf + OFF_TOK);

    const int tid = threadIdx.x;
    const int b0  = blockIdx.x * BB;

    // ------------- role decode + weights into registers -------------
    u64 wA[16], wB[16];
    u64 bqA = 0ull, bqB = 0ull;
    const char* sread = sbuf;
    float* oA = P3f;
    int coffs = 96, rowl = 192;
    const bool haveG = (tid < 336);
    if (tid < 192) {
        int uh = tid / 48, q = tid % 48;
        int u0 = uh * 16;
        #pragma unroll
        for (int uu = 0; uu < 16; uu++) {
            float2 a = *(const float2*)&kh2[(u0 + uu) * 192 + 2 * q];
            float2 b = *(const float2*)&kh2[(u0 + uu) * 192 + 2 * q + 96];
            wA[uu] = pk2(a.x, a.y); wB[uu] = pk2(b.x, b.y);
        }
        if (uh == 0) {
            float2 a = *(const float2*)&b2[192 + 2 * q];
            float2 b = *(const float2*)&b2[288 + 2 * q];
            bqA = pk2(a.x, a.y); bqB = pk2(b.x, b.y);
        }
        sread = sbuf + OFF_H2S + u0 * 48;
        oA = P3f + uh * 768 + 2 * q;
    } else if (tid < 288) {
        int t = tid - 192;
        int uh = t / 48, q = t % 48;
        int u0 = uh * 16;
        #pragma unroll
        for (int uu = 0; uu < 16; uu++) {
            float2 a = *(const float2*)&kx2[(u0 + uu) * 192 + 2 * q];
            float2 b = *(const float2*)&kx2[(u0 + uu) * 192 + 2 * q + 96];
            wA[uu] = pk2(a.x, a.y); wB[uu] = pk2(b.x, b.y);
        }
        if (uh == 0) {
            float2 a = *(const float2*)&b2[2 * q];
            float2 b = *(const float2*)&b2[96 + 2 * q];
            bqA = pk2(a.x, a.y); bqB = pk2(b.x, b.y);
        }
        sread = sbuf + OFF_H1S + u0 * 48;
        oA = P2f + uh * 768 + 2 * q;
    } else if (tid < 336) {
        int t = tid - 288;
        int uh = t / 24, q = t % 24;
        int u0 = uh * 16;
        #pragma unroll
        for (int uu = 0; uu < 16; uu++) {
            float2 a = *(const float2*)&kh1[(u0 + uu) * 96 + 2 * q];
            float2 b = *(const float2*)&kh1[(u0 + uu) * 96 + 2 * q + 48];
            wA[uu] = pk2(a.x, a.y); wB[uu] = pk2(b.x, b.y);
        }
        if (uh == 0) {
            float2 a = *(const float2*)&b1[96 + 2 * q];
            float2 b = *(const float2*)&b1[144 + 2 * q];
            bqA = pk2(a.x, a.y); bqB = pk2(b.x, b.y);
        }
        sread = sbuf + OFF_H1S + u0 * 48;
        oA = P1f + uh * 384 + 2 * q;
        coffs = 48; rowl = 96;
    }
    // P2 parity stride (floats): only group-G2 threads use it
    const int po = (tid >= 192 && tid < 288) ? 1536 : 0;

    // gather mapping: group1 threads gi = tid-192 in [0,160) cover 384 loads
    const int gi = tid - 192;
    int gb0 = 0, gj0 = 0, gb1 = 0, gj1 = 0, gb2 = 0, gj2 = 0;
    if (gi >= 0) {
        gb0 = gi / 96;          gj0 = gi % 96;
        gb1 = (gi + 160) / 96;  gj1 = (gi + 160) % 96;
        if (gi < 64) { gb2 = (gi + 320) / 96; gj2 = (gi + 320) % 96; }
    }

    // ------------- prologue -------------
    for (int i = tid; i < 576; i += NT) ((u64*)sbuf)[i] = 0ull;  // h1s + h2s
    if (gi >= 0 && gi < 128) {
        int b = gi >> 5, o = gi & 31;
        tok[b * 32 + o] = tokens[(b0 + b) * TT + o];
    }
    __syncthreads();
    for (int i = tid; i < 384; i += NT) {
        int b = i / 96, j = i - 96 * (i / 96);
        xg1[i]       = __ldg(&g_proj1[tok[b * 32 + 0] * 96 + j]);
        xg1[384 + i] = __ldg(&g_proj1[tok[b * 32 + 1] * 96 + j]);
    }
    __syncthreads();
    // GRU1 step 0 (h=0 -> recurrent term = bias)
    if (tid < 64) {
        int u = tid & 31, c = tid >> 5;
        int r0 = (2 * c) * 96 + u, r1 = r0 + 96;
        float bz = b1[96 + u], br = b1[128 + u], bhv = b1[160 + u];
        float n0 = gru1s(xg1[r0], bz, xg1[r0 + 32], br, xg1[r0 + 64], bhv, 0.0f);
        float n1 = gru1s(xg1[r1], bz, xg1[r1 + 32], br, xg1[r1 + 64], bhv, 0.0f);
        h1s[u * 6 + 2 * c]     = pk2(n0, n0);
        h1s[u * 6 + 2 * c + 1] = pk2(n1, n1);
    }
    __syncthreads();

    // ================= split pipelines (4-deep xg2 ring) =================
    // xg2(k) ready:    group1 arrives, group2 syncs  on bar 3+(k&3), count 352
    // xg2(k) consumed: group2 arrives, group1 syncs  on bar 7+(k&3), count 352
    if (tid < 192) {
        // -------- Group 2: GRU2 pipeline (6 warps) --------
        #pragma unroll 2
        for (int k = 0; k < TT; k++) {
            // A2: hm2 partials -> P3
            {
                u64 aA0 = bqA, aA1 = bqA, aA2 = bqA, aA3 = bqA;
                u64 aB0 = bqB, aB1 = bqB, aB2 = bqB, aB3 = bqB;
                #pragma unroll
                for (int uu = 0; uu < 16; uu++) {
                    ulonglong2 hA = *(const ulonglong2*)(sread + uu * 48);
                    ulonglong2 hB = *(const ulonglong2*)(sread + uu * 48 + 16);
                    u64 w0 = wA[uu], w1 = wB[uu];
                    aA0 = ffma2(w0, hA.x, aA0); aA1 = ffma2(w0, hA.y, aA1);
                    aB0 = ffma2(w1, hA.x, aB0); aB1 = ffma2(w1, hA.y, aB1);
                    aA2 = ffma2(w0, hB.x, aA2); aA3 = ffma2(w0, hB.y, aA3);
                    aB2 = ffma2(w1, hB.x, aB2); aB3 = ffma2(w1, hB.y, aB3);
                }
                *(u64*)&oA[0]   = aA0;
                *(u64*)&oA[192] = aA1;
                *(u64*)&oA[384] = aA2;
                *(u64*)&oA[576] = aA3;
                *(u64*)&oA[96]  = aB0;
                *(u64*)&oA[288] = aB1;
                *(u64*)&oA[480] = aB2;
                *(u64*)&oA[672] = aB3;
            }
            bar_sync_r(3 + (k & 3), 352);   // xg2(k) ready; orders A2 -> B2
            // B2: GRU2 gates
            {
                const float* PB = P2f + (k & 3) * 1536;
                #define GP2(idx) (PB[(idx)] + PB[768 + (idx)])
                #define GP4(idx) ((P3f[(idx)] + P3f[768 + (idx)]) + (P3f[1536 + (idx)] + P3f[2304 + (idx)]))
                int u = tid & 63, b = tid >> 6;
                int r = b * 192 + u;
                float xz = GP2(r), xr = GP2(r + 64), xh = GP2(r + 128);
                float hz = GP4(r), hr = GP4(r + 64), hh = GP4(r + 128);
                float o, dmy;
                upk2(h2s[u * 6 + b], o, dmy);
                float n = gru1s(xz, hz, xr, hr, xh, hh, o);
                h2s[u * 6 + b] = pk2(n, n);
                if (tid < 64) {
                    int r2 = 3 * 192 + tid;
                    float xz2 = GP2(r2), xr2 = GP2(r2 + 64), xh2 = GP2(r2 + 128);
                    float hz2 = GP4(r2), hr2 = GP4(r2 + 64), hh2 = GP4(r2 + 128);
                    float o2;
                    upk2(h2s[tid * 6 + 3], o2, dmy);
                    float n2 = gru1s(xz2, hz2, xr2, hr2, xh2, hh2, o2);
                    h2s[tid * 6 + 3] = pk2(n2, n2);
                }
            }
            bar_arrive_r(7 + (k & 3), 352); // xg2(k) consumed
            BAR_SYNC(2, 192);               // h2 visible before A2(k+1)
        }
    } else {
        // -------- Group 1: GRU1 pipeline (5 warps) --------
        float gv0 = 0.0f, gv1 = 0.0f, gv2 = 0.0f;
        #pragma unroll 2
        for (int k = 0; k < TT; k++) {
            if (k >= 4) bar_sync_r(7 + (k & 3), 352);   // P2[k&3] free
            // A1: gather issue + G2/G1 GEMMs
            if (k < TT - 2) {
                int slot = (k + 2) & 31;
                gv0 = __ldg(&g_proj1[tok[gb0 * 32 + slot] * 96 + gj0]);
                gv1 = __ldg(&g_proj1[tok[gb1 * 32 + slot] * 96 + gj1]);
                if (gi < 64)
                    gv2 = __ldg(&g_proj1[tok[gb2 * 32 + slot] * 96 + gj2]);
            }
            if (haveG) {
                u64 aA0 = bqA, aA1 = bqA, aA2 = bqA, aA3 = bqA;
                u64 aB0 = bqB, aB1 = bqB, aB2 = bqB, aB3 = bqB;
                #pragma unroll
                for (int uu = 0; uu < 16; uu++) {
                    ulonglong2 hA = *(const ulonglong2*)(sread + uu * 48);
                    ulonglong2 hB = *(const ulonglong2*)(sread + uu * 48 + 16);
                    u64 w0 = wA[uu], w1 = wB[uu];
                    aA0 = ffma2(w0, hA.x, aA0); aA1 = ffma2(w0, hA.y, aA1);
                    aB0 = ffma2(w1, hA.x, aB0); aB1 = ffma2(w1, hA.y, aB1);
                    aA2 = ffma2(w0, hB.x, aA2); aA3 = ffma2(w0, hB.y, aA3);
                    aB2 = ffma2(w1, hB.x, aB2); aB3 = ffma2(w1, hB.y, aB3);
                }
                float* o = oA + (k & 3) * po;
                *(u64*)&o[0]                = aA0;
                *(u64*)&o[rowl]             = aA1;
                *(u64*)&o[2 * rowl]         = aA2;
                *(u64*)&o[3 * rowl]         = aA3;
                *(u64*)&o[coffs]            = aB0;
                *(u64*)&o[rowl + coffs]     = aB1;
                *(u64*)&o[2 * rowl + coffs] = aB2;
                *(u64*)&o[3 * rowl + coffs] = aB3;
            }
            bar_arrive_r(3 + (k & 3), 352); // xg2(k) ready for group2
            BAR_SYNC(1, 160);               // P1 full (A1 -> B1)
            // B1: GRU1 gates (step k+1) + gather stores + token reload
            if (gi < 128 && k < TT - 1) {
                int u = gi & 31, b = gi >> 5;
                const float* xb = xg1 + ((k + 1) & 1) * 384;
                int r = b * 96 + u;
                #define GP1(idx) (P1f[(idx)] + P1f[384 + (idx)])
                float hz = GP1(r), hr = GP1(r + 32), hh = GP1(r + 64);
                float o, dmy;
                upk2(h1s[u * 6 + b], o, dmy);
                float n = gru1s(xb[r], hz, xb[r + 32], hr, xb[r + 64], hh, o);
                h1s[u * 6 + b] = pk2(n, n);
            }
            if (k < TT - 2) {
                float* xb = xg1 + ((k + 2) & 1) * 384;
                xb[gi] = gv0;
                xb[gi + 160] = gv1;
                if (gi < 64) xb[gi + 320] = gv2;
            }
            if (((k + 3) & 31) == 0 && (k + 3) < TT && gi < 128) {
                int b = gi >> 5, o = gi & 31;
                tok[b * 32 + o] = tokens[(b0 + b) * TT + (k + 3) + o];
            }
            BAR_SYNC(1, 160);               // h1/xg1 ready before A1(k+1)
        }
    }
    __syncthreads();

    // ================= Epilogue: GLU + dense + sigmoid (exact math) =========
    float* ags = P3f;   // [4][256] alias
    float* gws = (float*)(sbuf + OFF_P1);   // [4][128] alias
    if (tid < 256) {
        int c = tid;
        float bgv = bg[c];
        u64 acc0 = pk2(bgv, bgv), acc1 = acc0;
        #pragma unroll
        for (int u = 0; u < 64; u++) {
            const u64* hr = h2s + u * 6;
            float wv = __ldg(&wg[u * 256 + c]);
            u64 w = pk2(wv, wv);
            float f0, f1, f2, f3, d_;
            upk2(hr[0], f0, d_); upk2(hr[1], f1, d_);
            upk2(hr[2], f2, d_); upk2(hr[3], f3, d_);
            acc0 = ffma2(w, pk2(f0, f1), acc0);
            acc1 = ffma2(w, pk2(f2, f3), acc1);
        }
        float f0, f1;
        upk2(acc0, f0, f1); ags[0 * 256 + c] = f0; ags[1 * 256 + c] = f1;
        upk2(acc1, f0, f1); ags[2 * 256 + c] = f0; ags[3 * 256 + c] = f1;
    }
    __syncthreads();
    for (int i = tid; i < 512; i += NT) {
        int b = i >> 7, kk = i & 127;
        float g = ags[b * 256 + kk] * sgm(ags[b * 256 + 128 + kk]);
        gws[b * 128 + kk] = g * __ldg(&wd[kk]);
    }
    __syncthreads();
    if (tid < BB) {
        float s = bd[0];
        #pragma unroll
        for (int kk = 0; kk < 128; kk++) s += gws[tid * 128 + kk];
        out[b0 + tid] = sgm(s);
    }
}

// ---------------------------------------------------------------------------
extern "C" void kernel_launch(void* const* d_in, const int* in_sizes, int n_in,
                              void* d_out, int out_size) {
    (void)in_sizes; (void)n_in; (void)out_size;
    const int*   tokens = (const int*)  d_in[0];
    const float* emb    = (const float*)d_in[1];
    const float* kx1    = (const float*)d_in[2];
    const float* kh1    = (const float*)d_in[3];
    const float* b1     = (const float*)d_in[4];
    const float* kx2    = (const float*)d_in[5];
    const float* kh2    = (const float*)d_in[6];
    const float* b2     = (const float*)d_in[7];
    const float* wg     = (const float*)d_in[8];
    const float* bg     = (const float*)d_in[9];
    const float* wd     = (const float*)d_in[10];
    const float* bd     = (const float*)d_in[11];

    static int smem_set = 0;
    if (!smem_set) {
        cudaFuncSetAttribute(rnn_kernel,
                             cudaFuncAttributeMaxDynamicSharedMemorySize, SMEM_SZ);
        smem_set = 1;
    }

    proj_kernel<<<(VSZ + 15) / 16, 256>>>(emb, kx1, b1);
    rnn_kernel<<<BSZ / BB, NT, SMEM_SZ>>>(tokens, kh1, b1, kx2, kh2, b2,
                                          wg, bg, wd, bd, (float*)d_out);
}

// round 17
// speedup vs baseline: 1.0246x; 1.0246x over previous
#include <cuda_runtime.h>

#define VSZ 50257
#define Dk  50
#define TT  1024
#define BSZ 1024
#define BB  4
#define NT  352

// Precomputed emb @ kx1 + b1[0] table: [V, 96] fp32 (L2-resident, 19.3MB)
__device__ float g_proj1[VSZ * 96];

typedef unsigned long long u64;

__device__ __forceinline__ u64 pk2(float a, float b) {
    u64 r; asm("mov.b64 %0, {%1, %2};" : "=l"(r) : "f"(a), "f"(b)); return r;
}
__device__ __forceinline__ void upk2(u64 v, float& a, float& b) {
    asm("mov.b64 {%0, %1}, %2;" : "=f"(a), "=f"(b) : "l"(v));
}
__device__ __forceinline__ u64 ffma2(u64 a, u64 b, u64 c) {
    u64 d; asm("fma.rn.f32x2 %0, %1, %2, %3;" : "=l"(d) : "l"(a), "l"(b), "l"(c)); return d;
}
// exact (epilogue only)
__device__ __forceinline__ float sgm(float x) { return 1.0f / (1.0f + __expf(-x)); }
// HW tanh path (hot loop): 1 MUFU per evaluation
__device__ __forceinline__ float tanha(float x) {
    float y; asm("tanh.approx.f32 %0, %1;" : "=f"(y) : "f"(x)); return y;
}
__device__ __forceinline__ float sgm_fast(float x) {
    return fmaf(tanha(0.5f * x), 0.5f, 0.5f);
}

__device__ __forceinline__ float gru1s(float xz, float hz, float xr, float hr,
                                       float xh, float hh, float hold) {
    float z = sgm_fast(xz + hz);
    float r = sgm_fast(xr + hr);
    float c = tanha(xh + r * hh);
    return fmaf(z, hold - c, c);     // == z*h + (1-z)*c
}

__device__ __forceinline__ void bar_sync_r(int id, int cnt) {
    asm volatile("bar.sync %0, %1;" :: "r"(id), "r"(cnt) : "memory");
}
__device__ __forceinline__ void bar_arrive_r(int id, int cnt) {
    asm volatile("bar.arrive %0, %1;" :: "r"(id), "r"(cnt) : "memory");
}
#define BAR_SYNC(id, cnt) asm volatile("bar.sync %0, %1;" :: "n"(id), "n"(cnt) : "memory")

// ---------------------------------------------------------------------------
__global__ void proj_kernel(const float* __restrict__ emb,
                            const float* __restrict__ kx1,
                            const float* __restrict__ b1) {
    __shared__ float kxs[Dk * 96];
    __shared__ float embs[16 * Dk];
    int tid = threadIdx.x;
    for (int i = tid; i < Dk * 96; i += 256) kxs[i] = kx1[i];
    int vbase = blockIdx.x * 16;
    for (int i = tid; i < 16 * Dk; i += 256) {
        int r = i / Dk, d = i - r * Dk;
        int v = vbase + r;
        embs[i] = (v < VSZ) ? emb[v * Dk + d] : 0.0f;
    }
    __syncthreads();
    for (int i = tid; i < 16 * 96; i += 256) {
        int r = i / 96, j = i - r * 96;
        int v = vbase + r;
        if (v >= VSZ) continue;
        float acc = b1[j];
        #pragma unroll
        for (int d = 0; d < Dk; d++)
            acc = fmaf(embs[r * Dk + d], kxs[d * 96 + j], acc);
        g_proj1[v * 96 + j] = acc;
    }
}

// ---------------------------------------------------------------------------
// Shared layout (bytes), BB=4 batches per CTA.
// States: [u][6] u64 rows (48B, 16B-aligned; dup pairs (h,h), slots 0-3 = b).
// P3: 4 u-half bufs x [4][192] f32 (group2 internal).
// P2: 2 parity x 2 u-half bufs x [4][192] f32 (cross, double-buffered).
// P1: 2 u-half bufs x [4][96] f32 (group1 internal).
// ---------------------------------------------------------------------------
#define OFF_H1S  0        // 32*6 u64 = 1536
#define OFF_H2S  1536     // 64*6 u64 = 3072
#define OFF_P3   4608     // 4 x 3072 = 12288
#define OFF_P2   16896    // 4 x 3072 = 12288 (parity*1536fl + uh*768fl)
#define OFF_P1   29184    // 2 x 1536 = 3072
#define OFF_XG1  32256    // 2 x 1536 = 3072
#define OFF_TOK  35328    // [4][32] int = 512
#define SMEM_SZ  35840

__global__ void __launch_bounds__(NT, 2) rnn_kernel(
    const int*   __restrict__ tokens,
    const float* __restrict__ kh1,   // [32][96]
    const float* __restrict__ b1,    // [2][96]
    const float* __restrict__ kx2,   // [32][192]
    const float* __restrict__ kh2,   // [64][192]
    const float* __restrict__ b2,    // [2][192]
    const float* __restrict__ wg,    // [64][256]
    const float* __restrict__ bg,    // [256]
    const float* __restrict__ wd,    // [128]
    const float* __restrict__ bd,    // [1]
    float*       __restrict__ out)
{
    extern __shared__ char sbuf[];
    u64*   h1s = (u64*)(sbuf + OFF_H1S);   // [u][6]
    u64*   h2s = (u64*)(sbuf + OFF_H2S);   // [u][6]
    float* P3f = (float*)(sbuf + OFF_P3);
    float* P2f = (float*)(sbuf + OFF_P2);
    float* P1f = (float*)(sbuf + OFF_P1);
    float* xg1 = (float*)(sbuf + OFF_XG1); // 2 bufs x 384 floats
    int*   tok = (int*)(sbuf + OFF_TOK);

    const int tid = threadIdx.x;
    const int b0  = blockIdx.x * BB;

    // ------------- role decode + weights into registers -------------
    u64 wA[16], wB[16];
    u64 bqA = 0ull, bqB = 0ull;
    const char* sread = sbuf;
    float* oA = P3f;
    int coffs = 96, rowl = 192, po = 0;
    const bool haveG = (tid < 336);
    if (tid < 192) {
        int uh = tid / 48, q = tid % 48;
        int u0 = uh * 16;
        #pragma unroll
        for (int uu = 0; uu < 16; uu++) {
            float2 a = *(const float2*)&kh2[(u0 + uu) * 192 + 2 * q];
            float2 b = *(const float2*)&kh2[(u0 + uu) * 192 + 2 * q + 96];
            wA[uu] = pk2(a.x, a.y); wB[uu] = pk2(b.x, b.y);
        }
        if (uh == 0) {
            float2 a = *(const float2*)&b2[192 + 2 * q];
            float2 b = *(const float2*)&b2[288 + 2 * q];
            bqA = pk2(a.x, a.y); bqB = pk2(b.x, b.y);
        }
        sread = sbuf + OFF_H2S + u0 * 48;
        oA = P3f + uh * 768 + 2 * q;
    } else if (tid < 288) {
        int t = tid - 192;
        int uh = t / 48, q = t % 48;
        int u0 = uh * 16;
        #pragma unroll
        for (int uu = 0; uu < 16; uu++) {
            float2 a = *(const float2*)&kx2[(u0 + uu) * 192 + 2 * q];
            float2 b = *(const float2*)&kx2[(u0 + uu) * 192 + 2 * q + 96];
            wA[uu] = pk2(a.x, a.y); wB[uu] = pk2(b.x, b.y);
        }
        if (uh == 0) {
            float2 a = *(const float2*)&b2[2 * q];
            float2 b = *(const float2*)&b2[96 + 2 * q];
            bqA = pk2(a.x, a.y); bqB = pk2(b.x, b.y);
        }
        sread = sbuf + OFF_H1S + u0 * 48;
        oA = P2f + uh * 768 + 2 * q;
        po = 1536;
    } else if (tid < 336) {
        int t = tid - 288;
        int uh = t / 24, q = t % 24;
        int u0 = uh * 16;
        #pragma unroll
        for (int uu = 0; uu < 16; uu++) {
            float2 a = *(const float2*)&kh1[(u0 + uu) * 96 + 2 * q];
            float2 b = *(const float2*)&kh1[(u0 + uu) * 96 + 2 * q + 48];
            wA[uu] = pk2(a.x, a.y); wB[uu] = pk2(b.x, b.y);
        }
        if (uh == 0) {
            float2 a = *(const float2*)&b1[96 + 2 * q];
            float2 b = *(const float2*)&b1[144 + 2 * q];
            bqA = pk2(a.x, a.y); bqB = pk2(b.x, b.y);
        }
        sread = sbuf + OFF_H1S + u0 * 48;
        oA = P1f + uh * 384 + 2 * q;
        coffs = 48; rowl = 96;
    }

    // gather mapping: group1 threads gi = tid-192 in [0,160) cover 384 loads
    const int gi = tid - 192;
    int gb0 = 0, gj0 = 0, gb1 = 0, gj1 = 0, gb2 = 0, gj2 = 0;
    if (gi >= 0) {
        gb0 = gi / 96;          gj0 = gi % 96;
        gb1 = (gi + 160) / 96;  gj1 = (gi + 160) % 96;
        if (gi < 64) { gb2 = (gi + 320) / 96; gj2 = (gi + 320) % 96; }
    }

    // ------------- prologue -------------
    for (int i = tid; i < 576; i += NT) ((u64*)sbuf)[i] = 0ull;  // h1s + h2s
    if (gi >= 0 && gi < 128) {
        int b = gi >> 5, o = gi & 31;
        tok[b * 32 + o] = tokens[(b0 + b) * TT + o];
    }
    __syncthreads();
    for (int i = tid; i < 384; i += NT) {
        int b = i / 96, j = i - 96 * (i / 96);
        xg1[i]       = __ldg(&g_proj1[tok[b * 32 + 0] * 96 + j]);
        xg1[384 + i] = __ldg(&g_proj1[tok[b * 32 + 1] * 96 + j]);
    }
    __syncthreads();
    // GRU1 step 0 (h=0 -> recurrent term = bias)
    if (tid < 64) {
        int u = tid & 31, c = tid >> 5;
        int r0 = (2 * c) * 96 + u, r1 = r0 + 96;
        float bz = b1[96 + u], br = b1[128 + u], bhv = b1[160 + u];
        float n0 = gru1s(xg1[r0], bz, xg1[r0 + 32], br, xg1[r0 + 64], bhv, 0.0f);
        float n1 = gru1s(xg1[r1], bz, xg1[r1 + 32], br, xg1[r1 + 64], bhv, 0.0f);
        h1s[u * 6 + 2 * c]     = pk2(n0, n0);
        h1s[u * 6 + 2 * c + 1] = pk2(n1, n1);
    }
    __syncthreads();

    // ================= split pipelines (parity barriers) =================
    // xg2(k) ready:    group1 arrives, group2 syncs  on bar 3+(k&1), count 352
    // xg2(k) consumed: group2 arrives, group1 syncs  on bar 5+(k&1), count 352
    if (tid < 192) {
        // -------- Group 2: GRU2 pipeline (6 warps) --------
        #pragma unroll 2
        for (int k = 0; k < TT; k++) {
            // A2: hm2 partials -> P3
            {
                u64 aA0 = bqA, aA1 = bqA, aA2 = bqA, aA3 = bqA;
                u64 aB0 = bqB, aB1 = bqB, aB2 = bqB, aB3 = bqB;
                #pragma unroll
                for (int uu = 0; uu < 16; uu++) {
                    ulonglong2 hA = *(const ulonglong2*)(sread + uu * 48);
                    ulonglong2 hB = *(const ulonglong2*)(sread + uu * 48 + 16);
                    u64 w0 = wA[uu], w1 = wB[uu];
                    aA0 = ffma2(w0, hA.x, aA0); aA1 = ffma2(w0, hA.y, aA1);
                    aB0 = ffma2(w1, hA.x, aB0); aB1 = ffma2(w1, hA.y, aB1);
                    aA2 = ffma2(w0, hB.x, aA2); aA3 = ffma2(w0, hB.y, aA3);
                    aB2 = ffma2(w1, hB.x, aB2); aB3 = ffma2(w1, hB.y, aB3);
                }
                *(u64*)&oA[0]   = aA0;
                *(u64*)&oA[192] = aA1;
                *(u64*)&oA[384] = aA2;
                *(u64*)&oA[576] = aA3;
                *(u64*)&oA[96]  = aB0;
                *(u64*)&oA[288] = aB1;
                *(u64*)&oA[480] = aB2;
                *(u64*)&oA[672] = aB3;
            }
            bar_sync_r(3 + (k & 1), 352);   // xg2(k) ready; orders A2 -> B2
            // B2: GRU2 gates
            {
                const float* PB = P2f + (k & 1) * 1536;
                #define GP2(idx) (PB[(idx)] + PB[768 + (idx)])
                #define GP4(idx) ((P3f[(idx)] + P3f[768 + (idx)]) + (P3f[1536 + (idx)] + P3f[2304 + (idx)]))
                int u = tid & 63, b = tid >> 6;
                int r = b * 192 + u;
                float xz = GP2(r), xr = GP2(r + 64), xh = GP2(r + 128);
                float hz = GP4(r), hr = GP4(r + 64), hh = GP4(r + 128);
                float o, dmy;
                upk2(h2s[u * 6 + b], o, dmy);
                float n = gru1s(xz, hz, xr, hr, xh, hh, o);
                h2s[u * 6 + b] = pk2(n, n);
                if (tid < 64) {
                    int r2 = 3 * 192 + tid;
                    float xz2 = GP2(r2), xr2 = GP2(r2 + 64), xh2 = GP2(r2 + 128);
                    float hz2 = GP4(r2), hr2 = GP4(r2 + 64), hh2 = GP4(r2 + 128);
                    float o2;
                    upk2(h2s[tid * 6 + 3], o2, dmy);
                    float n2 = gru1s(xz2, hz2, xr2, hr2, xh2, hh2, o2);
                    h2s[tid * 6 + 3] = pk2(n2, n2);
                }
            }
            bar_arrive_r(5 + (k & 1), 352); // xg2(k) consumed
            BAR_SYNC(2, 192);               // h2 visible before A2(k+1)
        }
    } else {
        // -------- Group 1: GRU1 pipeline (5 warps) --------
        float gv0 = 0.0f, gv1 = 0.0f, gv2 = 0.0f;
        #pragma unroll 2
        for (int k = 0; k < TT; k++) {
            if (k >= 2) bar_sync_r(5 + (k & 1), 352);   // P2[k&1] free
            // A1: gather issue + G2/G1 GEMMs
            if (k < TT - 2) {
                int slot = (k + 2) & 31;
                gv0 = __ldg(&g_proj1[tok[gb0 * 32 + slot] * 96 + gj0]);
                gv1 = __ldg(&g_proj1[tok[gb1 * 32 + slot] * 96 + gj1]);
                if (gi < 64)
                    gv2 = __ldg(&g_proj1[tok[gb2 * 32 + slot] * 96 + gj2]);
            }
            if (haveG) {
                u64 aA0 = bqA, aA1 = bqA, aA2 = bqA, aA3 = bqA;
                u64 aB0 = bqB, aB1 = bqB, aB2 = bqB, aB3 = bqB;
                #pragma unroll
                for (int uu = 0; uu < 16; uu++) {
                    ulonglong2 hA = *(const ulonglong2*)(sread + uu * 48);
                    ulonglong2 hB = *(const ulonglong2*)(sread + uu * 48 + 16);
                    u64 w0 = wA[uu], w1 = wB[uu];
                    aA0 = ffma2(w0, hA.x, aA0); aA1 = ffma2(w0, hA.y, aA1);
                    aB0 = ffma2(w1, hA.x, aB0); aB1 = ffma2(w1, hA.y, aB1);
                    aA2 = ffma2(w0, hB.x, aA2); aA3 = ffma2(w0, hB.y, aA3);
                    aB2 = ffma2(w1, hB.x, aB2); aB3 = ffma2(w1, hB.y, aB3);
                }
                float* o = oA + (k & 1) * po;
                *(u64*)&o[0]                = aA0;
                *(u64*)&o[rowl]             = aA1;
                *(u64*)&o[2 * rowl]         = aA2;
                *(u64*)&o[3 * rowl]         = aA3;
                *(u64*)&o[coffs]            = aB0;
                *(u64*)&o[rowl + coffs]     = aB1;
                *(u64*)&o[2 * rowl + coffs] = aB2;
                *(u64*)&o[3 * rowl + coffs] = aB3;
            }
            bar_arrive_r(3 + (k & 1), 352); // xg2(k) ready for group2
            BAR_SYNC(1, 160);               // P1 full (A1 -> B1)
            // B1: GRU1 gates (step k+1) + gather stores + token reload
            if (gi < 128 && k < TT - 1) {
                int u = gi & 31, b = gi >> 5;
                const float* xb = xg1 + ((k + 1) & 1) * 384;
                int r = b * 96 + u;
                #define GP1(idx) (P1f[(idx)] + P1f[384 + (idx)])
                float hz = GP1(r), hr = GP1(r + 32), hh = GP1(r + 64);
                float o, dmy;
                upk2(h1s[u * 6 + b], o, dmy);
                float n = gru1s(xb[r], hz, xb[r + 32], hr, xb[r + 64], hh, o);
                h1s[u * 6 + b] = pk2(n, n);
            }
            if (k < TT - 2) {
                float* xb = xg1 + ((k + 2) & 1) * 384;
                xb[gi] = gv0;
                xb[gi + 160] = gv1;
                if (gi < 64) xb[gi + 320] = gv2;
            }
            if (((k + 3) & 31) == 0 && (k + 3) < TT && gi < 128) {
                int b = gi >> 5, o = gi & 31;
                tok[b * 32 + o] = tokens[(b0 + b) * TT + (k + 3) + o];
            }
            BAR_SYNC(1, 160);               // h1/xg1 ready before A1(k+1)
        }
    }
    __syncthreads();

    // ================= Epilogue: GLU + dense + sigmoid (exact math) =========
    float* ags = P3f;   // [4][256] alias
    float* gws = P2f;   // [4][128] alias
    if (tid < 256) {
        int c = tid;
        float bgv = bg[c];
        u64 acc0 = pk2(bgv, bgv), acc1 = acc0;
        #pragma unroll
        for (int u = 0; u < 64; u++) {
            const u64* hr = h2s + u * 6;
            float wv = __ldg(&wg[u * 256 + c]);
            u64 w = pk2(wv, wv);
            float f0, f1, f2, f3, d_;
            upk2(hr[0], f0, d_); upk2(hr[1], f1, d_);
            upk2(hr[2], f2, d_); upk2(hr[3], f3, d_);
            acc0 = ffma2(w, pk2(f0, f1), acc0);
            acc1 = ffma2(w, pk2(f2, f3), acc1);
        }
        float f0, f1;
        upk2(acc0, f0, f1); ags[0 * 256 + c] = f0; ags[1 * 256 + c] = f1;
        upk2(acc1, f0, f1); ags[2 * 256 + c] = f0; ags[3 * 256 + c] = f1;
    }
    __syncthreads();
    for (int i = tid; i < 512; i += NT) {
        int b = i >> 7, kk = i & 127;
        float g = ags[b * 256 + kk] * sgm(ags[b * 256 + 128 + kk]);
        gws[b * 128 + kk] = g * __ldg(&wd[kk]);
    }
    __syncthreads();
    if (tid < BB) {
        float s = bd[0];
        #pragma unroll
        for (int kk = 0; kk < 128; kk++) s += gws[tid * 128 + kk];
        out[b0 + tid] = sgm(s);
    }
}

// ---------------------------------------------------------------------------
extern "C" void kernel_launch(void* const* d_in, const int* in_sizes, int n_in,
                              void* d_out, int out_size) {
    (void)in_sizes; (void)n_in; (void)out_size;
    const int*   tokens = (const int*)  d_in[0];
    const float* emb    = (const float*)d_in[1];
    const float* kx1    = (const float*)d_in[2];
    const float* kh1    = (const float*)d_in[3];
    const float* b1     = (const float*)d_in[4];
    const float* kx2    = (const float*)d_in[5];
    const float* kh2    = (const float*)d_in[6];
    const float* b2     = (const float*)d_in[7];
    const float* wg     = (const float*)d_in[8];
    const float* bg     = (const float*)d_in[9];
    const float* wd     = (const float*)d_in[10];
    const float* bd     = (const float*)d_in[11];

    static int smem_set = 0;
    if (!smem_set) {
        cudaFuncSetAttribute(rnn_kernel,
                             cudaFuncAttributeMaxDynamicSharedMemorySize, SMEM_SZ);
        smem_set = 1;
    }

    proj_kernel<<<(VSZ + 15) / 16, 256>>>(emb, kx1, b1);
    rnn_kernel<<<BSZ / BB, NT, SMEM_SZ>>>(tokens, kh1, b1, kx2, kh2, b2,
                                          wg, bg, wd, bd, (float*)d_out);
}